// round 2
// baseline (speedup 1.0000x reference)
#include <cuda_runtime.h>
#include <cuda_bf16.h>
#include <cstdint>

// -------------------------------------------------------------------------
// CoralFocalLoss_MultiTask, single fused kernel.
//
// Per element (logit x, binary coral target tm):
//   loss = alpha(tm) * h(y),  y = tm ? x : -x,  alpha = tm ? 0.25 : 0.75
//   h(y) = sigmoid(-y)^2 * softplus(-y) = u^2 * (s - y)
//      t = e^y, u = 1/(1+t), s = log(1+t)
// Row loss scaled by class_weights[kl_t]. Outputs are means.
//
// 2 MUFU (EX2, LG2) per logit; reciprocal on the FMA pipe (bit trick +
// 2 Newton steps, ~6e-6 one-sided rel err).
//
// Finalization fused via threadfence-reduction: last block to arrive sums
// the per-block partials in fixed order (deterministic) and writes d_out.
// -------------------------------------------------------------------------

#define NBLOCKS 1184
#define NTHREADS 256

__device__ float        g_partials[NBLOCKS * 3];
__device__ unsigned int g_ticket = 0;   // zero-init at module load; reset by last block

__device__ __forceinline__ float fast_rcp(float a) {
    // valid for a = 1 + e^y in [1, ~inf); bit trick + 2 Newton iterations
    float u = __int_as_float(0x7EF311C3 - __float_as_int(a));
    u = u * (2.0f - a * u);
    u = u * (2.0f - a * u);
    return u;
}

__device__ __forceinline__ float coral_term(float x, bool tm) {
    float y     = tm ? x : -x;
    float alpha = tm ? 0.25f : 0.75f;
    float t = __expf(y);           // MUFU EX2 (+mul)
    float a = 1.0f + t;
    float u = fast_rcp(a);         // FMA pipe
    float s = __logf(a);           // MUFU LG2 (+mul)
    return alpha * (u * u) * (s - y);
}

__global__ void __launch_bounds__(NTHREADS)
coral_fused_kernel(const float* __restrict__ kl_logits,
                   const float* __restrict__ jsnm_logits,
                   const float* __restrict__ jsnl_logits,
                   const float* __restrict__ class_weights,
                   const int*   __restrict__ kl_t,
                   const int*   __restrict__ jsnm_t,
                   const int*   __restrict__ jsnl_t,
                   float* __restrict__ out,
                   int n)
{
    __shared__ float s_w[5];
    __shared__ bool  s_is_last;
    if (threadIdx.x < 5) s_w[threadIdx.x] = class_weights[threadIdx.x];
    __syncthreads();

    float sum_kl = 0.0f, sum_m = 0.0f, sum_l = 0.0f;

    const int npairs = n >> 1;
    const int stride = gridDim.x * blockDim.x;

    for (int p = blockIdx.x * blockDim.x + threadIdx.x; p < npairs; p += stride) {
        int i0 = 2 * p;

        int2 kt2 = reinterpret_cast<const int2*>(kl_t)[p];
        int2 mt2 = reinterpret_cast<const int2*>(jsnm_t)[p];
        int2 lt2 = reinterpret_cast<const int2*>(jsnl_t)[p];
        float w0 = s_w[kt2.x];
        float w1 = s_w[kt2.y];

        // kl logits: two aligned float4 rows
        float4 q0 = reinterpret_cast<const float4*>(kl_logits)[i0];
        float4 q1 = reinterpret_cast<const float4*>(kl_logits)[i0 + 1];
        float rk0 = coral_term(q0.x, 0 < kt2.x) + coral_term(q0.y, 1 < kt2.x)
                  + coral_term(q0.z, 2 < kt2.x) + coral_term(q0.w, 3 < kt2.x);
        float rk1 = coral_term(q1.x, 0 < kt2.y) + coral_term(q1.y, 1 < kt2.y)
                  + coral_term(q1.z, 2 < kt2.y) + coral_term(q1.w, 3 < kt2.y);
        sum_kl += w0 * rk0 + w1 * rk1;

        // jsnm logits: 6 floats = three aligned float2
        {
            const float2* pm = reinterpret_cast<const float2*>(jsnm_logits + 6 * (size_t)p);
            float2 a = pm[0], b = pm[1], c = pm[2];
            float rm0 = coral_term(a.x, 0 < mt2.x) + coral_term(a.y, 1 < mt2.x)
                      + coral_term(b.x, 2 < mt2.x);
            float rm1 = coral_term(b.y, 0 < mt2.y) + coral_term(c.x, 1 < mt2.y)
                      + coral_term(c.y, 2 < mt2.y);
            sum_m += w0 * rm0 + w1 * rm1;
        }

        // jsnl logits: same layout
        {
            const float2* pl = reinterpret_cast<const float2*>(jsnl_logits + 6 * (size_t)p);
            float2 a = pl[0], b = pl[1], c = pl[2];
            float rl0 = coral_term(a.x, 0 < lt2.x) + coral_term(a.y, 1 < lt2.x)
                      + coral_term(b.x, 2 < lt2.x);
            float rl1 = coral_term(b.y, 0 < lt2.y) + coral_term(c.x, 1 < lt2.y)
                      + coral_term(c.y, 2 < lt2.y);
            sum_l += w0 * rl0 + w1 * rl1;
        }
    }

    // odd-n tail (n is even in this problem, but keep it correct)
    if ((n & 1) && blockIdx.x == 0 && threadIdx.x == 0) {
        int i = n - 1;
        int kt = kl_t[i], mt = jsnm_t[i], lt = jsnl_t[i];
        float w = s_w[kt];
        const float* q = kl_logits + 4 * (size_t)i;
        sum_kl += w * (coral_term(q[0], 0 < kt) + coral_term(q[1], 1 < kt)
                     + coral_term(q[2], 2 < kt) + coral_term(q[3], 3 < kt));
        const float* pm = jsnm_logits + 3 * (size_t)i;
        sum_m  += w * (coral_term(pm[0], 0 < mt) + coral_term(pm[1], 1 < mt)
                     + coral_term(pm[2], 2 < mt));
        const float* pl = jsnl_logits + 3 * (size_t)i;
        sum_l  += w * (coral_term(pl[0], 0 < lt) + coral_term(pl[1], 1 < lt)
                     + coral_term(pl[2], 2 < lt));
    }

    // -------- block reduction (deterministic) --------
    const unsigned FULL = 0xFFFFFFFFu;
    #pragma unroll
    for (int o = 16; o > 0; o >>= 1) {
        sum_kl += __shfl_down_sync(FULL, sum_kl, o);
        sum_m  += __shfl_down_sync(FULL, sum_m,  o);
        sum_l  += __shfl_down_sync(FULL, sum_l,  o);
    }

    __shared__ float s_red[3][NTHREADS / 32];
    int wid = threadIdx.x >> 5;
    int lid = threadIdx.x & 31;
    if (lid == 0) {
        s_red[0][wid] = sum_kl;
        s_red[1][wid] = sum_m;
        s_red[2][wid] = sum_l;
    }
    __syncthreads();

    if (threadIdx.x == 0) {
        float v0 = 0.0f, v1 = 0.0f, v2 = 0.0f;
        #pragma unroll
        for (int i = 0; i < NTHREADS / 32; i++) {
            v0 += s_red[0][i];
            v1 += s_red[1][i];
            v2 += s_red[2][i];
        }
        g_partials[blockIdx.x * 3 + 0] = v0;
        g_partials[blockIdx.x * 3 + 1] = v1;
        g_partials[blockIdx.x * 3 + 2] = v2;
        __threadfence();
        unsigned t = atomicInc(&g_ticket, gridDim.x - 1);
        s_is_last = (t == gridDim.x - 1);
    }
    __syncthreads();

    // -------- last block finalizes --------
    if (s_is_last) {
        float v0 = 0.0f, v1 = 0.0f, v2 = 0.0f;
        for (int i = threadIdx.x; i < NBLOCKS; i += NTHREADS) {
            v0 += g_partials[i * 3 + 0];
            v1 += g_partials[i * 3 + 1];
            v2 += g_partials[i * 3 + 2];
        }
        #pragma unroll
        for (int o = 16; o > 0; o >>= 1) {
            v0 += __shfl_down_sync(FULL, v0, o);
            v1 += __shfl_down_sync(FULL, v1, o);
            v2 += __shfl_down_sync(FULL, v2, o);
        }
        if (lid == 0) {
            s_red[0][wid] = v0;
            s_red[1][wid] = v1;
            s_red[2][wid] = v2;
        }
        __syncthreads();
        if (threadIdx.x == 0) {
            float t0 = 0.0f, t1 = 0.0f, t2 = 0.0f;
            #pragma unroll
            for (int i = 0; i < NTHREADS / 32; i++) {
                t0 += s_red[0][i];
                t1 += s_red[1][i];
                t2 += s_red[2][i];
            }
            float fn = (float)n;
            float l_kl   = t0 / (4.0f * fn);
            float l_jsnm = t1 / (3.0f * fn);
            float l_jsnl = t2 / (3.0f * fn);
            out[0] = (l_kl + l_jsnm + l_jsnl) * (1.0f / 3.0f);
            out[1] = l_kl;
            out[2] = l_jsnm;
            out[3] = l_jsnl;
            // atomicInc already wrapped g_ticket back to 0 (max = gridDim.x-1),
            // so the next graph replay starts clean.
        }
    }
}

extern "C" void kernel_launch(void* const* d_in, const int* in_sizes, int n_in,
                              void* d_out, int out_size)
{
    const float* kl_logits     = (const float*)d_in[0];
    const float* jsnm_logits   = (const float*)d_in[1];
    const float* jsnl_logits   = (const float*)d_in[2];
    const float* class_weights = (const float*)d_in[3];
    const int*   kl_t          = (const int*)d_in[4];
    const int*   jsnm_t        = (const int*)d_in[5];
    const int*   jsnl_t        = (const int*)d_in[6];

    int n = in_sizes[4];  // N samples (kl_t element count)

    coral_fused_kernel<<<NBLOCKS, NTHREADS>>>(
        kl_logits, jsnm_logits, jsnl_logits, class_weights,
        kl_t, jsnm_t, jsnl_t, (float*)d_out, n);
}